// round 5
// baseline (speedup 1.0000x reference)
#include <cuda_runtime.h>
#include <cuda_bf16.h>
#include <cstdint>

#define MAXN 40000
#define CAP  96

// ---------------- device scratch ----------------
__device__ int   g_deg[MAXN];
__device__ int   g_csrc[(size_t)MAXN * CAP];
__device__ float g_wgt [(size_t)MAXN * CAP];
__device__ float g_dinv[MAXN];
__device__ float g_bufA[(size_t)MAXN * 128];
__device__ float g_bufB[(size_t)MAXN * 128];
// B fragment images (hi / lo splits), in exact mma.sync B-register order
// layer offsets (u32): L1=0, L2=4096, L3=8192, L4=16384, L5=20480
__device__ uint32_t g_BfH[21504];
__device__ uint32_t g_BfL[21504];

// ---------------- helpers ----------------
__device__ __forceinline__ uint32_t smem_u32(const void* p) {
    uint32_t a;
    asm("{ .reg .u64 t; cvta.to.shared.u64 t, %1; cvt.u32.u64 %0, t; }"
        : "=r"(a) : "l"(p));
    return a;
}
__device__ __forceinline__ uint32_t pack_bf16(float x, float y) {
    __nv_bfloat162 p = __floats2bfloat162_rn(x, y);   // .x = x (low half)
    return *(uint32_t*)&p;
}
__device__ __forceinline__ void split_bf16(float v, __nv_bfloat16& h, float& lo) {
    h = __float2bfloat16_rn(v);
    lo = v - __bfloat162float(h);
}
__device__ __forceinline__ void ldm4(uint32_t* a, uint32_t addr) {
    asm volatile("ldmatrix.sync.aligned.m8n8.x4.shared.b16 {%0,%1,%2,%3}, [%4];"
                 : "=r"(a[0]), "=r"(a[1]), "=r"(a[2]), "=r"(a[3]) : "r"(addr));
}
__device__ __forceinline__ void mma_bf16(float* d, const uint32_t* a, uint2 b) {
    asm volatile("mma.sync.aligned.m16n8k16.row.col.f32.bf16.bf16.f32 "
                 "{%0,%1,%2,%3}, {%4,%5,%6,%7}, {%8,%9}, {%0,%1,%2,%3};"
                 : "+f"(d[0]), "+f"(d[1]), "+f"(d[2]), "+f"(d[3])
                 : "r"(a[0]), "r"(a[1]), "r"(a[2]), "r"(a[3]),
                   "r"(b.x), "r"(b.y));
}

// ---------------- graph build ----------------
__global__ void k_fill(const int* __restrict__ ei, int E) {
    int e = blockIdx.x * blockDim.x + threadIdx.x;
    if (e < E) {
        int d = ei[E + e];
        int s = ei[e];
        int pos = atomicAdd(&g_deg[d], 1);
        g_csrc[(size_t)d * CAP + pos] = s;
    }
}
__global__ void k_dinv(int n) {
    int i = blockIdx.x * blockDim.x + threadIdx.x;
    if (i < n) g_dinv[i] = rsqrtf((float)g_deg[i] + 1.0f);
}
__global__ void k_wgt(int n) {
    int idx = blockIdx.x * blockDim.x + threadIdx.x;
    int node = idx / CAP;
    int slot = idx - node * CAP;
    if (node >= n) return;
    int deg = g_deg[node];
    int degR = (deg + 3) & ~3;
    if (slot >= degR) return;
    size_t p = (size_t)node * CAP + slot;
    if (slot < deg) {
        int s = g_csrc[p];
        g_wgt[p] = g_dinv[node] * g_dinv[s];
    } else {
        g_csrc[p] = node;
        g_wgt[p] = 0.0f;
    }
}

// ---------------- B prep: W[K,NOUT] -> mma B-fragment images (hi/lo) ----------------
// image index = ((nt*KS + ks)*32 + lane)*2 + reg
// frag: b0 = {B[k0][n], B[k0+1][n]}, b1 = {B[k0+8][n], B[k0+9][n]},
//       k0 = ks*16 + (lane%4)*2, n = nt*8 + lane/4
template <int K, int NOUT>
__global__ void k_prepB(const float* __restrict__ W, uint32_t* __restrict__ dH,
                        uint32_t* __restrict__ dL) {
    constexpr int KS = K / 16;
    int idx = blockIdx.x * blockDim.x + threadIdx.x;
    if (idx >= (NOUT / 8) * KS * 32) return;
    int lane = idx & 31;
    int rest = idx >> 5;
    int ks = rest % KS;
    int nt = rest / KS;
    int n  = nt * 8 + (lane >> 2);
    int k0 = ks * 16 + (lane & 3) * 2;

    float v00 = W[(size_t)(k0 + 0) * NOUT + n];
    float v01 = W[(size_t)(k0 + 1) * NOUT + n];
    float v10 = W[(size_t)(k0 + 8) * NOUT + n];
    float v11 = W[(size_t)(k0 + 9) * NOUT + n];

    __nv_bfloat16 h00, h01, h10, h11;
    float l00, l01, l10, l11;
    split_bf16(v00, h00, l00); split_bf16(v01, h01, l01);
    split_bf16(v10, h10, l10); split_bf16(v11, h11, l11);

    int o = idx * 2;
    dH[o + 0] = pack_bf16(__bfloat162float(h00), __bfloat162float(h01));
    dH[o + 1] = pack_bf16(__bfloat162float(h10), __bfloat162float(h11));
    dL[o + 0] = pack_bf16(l00, l01);
    dL[o + 1] = pack_bf16(l10, l11);
}

// ---------------- tensor-core GEMM: C[M,Nout] = A[M,K] @ W (3-term bf16 split) ----------------
// CTA tile: 128 x NT. 8 warps: NWN = NT/16 warps across N, MT = NWN m16-tiles per warp.
template <int K, int NT, bool BIAS, bool RELU>
__global__ __launch_bounds__(256) void k_gemm_mma(
        const float* __restrict__ A, const uint32_t* __restrict__ BfH,
        const uint32_t* __restrict__ BfL, const float* __restrict__ bias,
        float* __restrict__ C, int M, int Nout) {
    constexpr int KS   = K / 16;
    constexpr int ROWB = K * 2;               // bytes per smem A row
    constexpr int ASZ  = 128 * K * 2;         // bytes per A split image
    constexpr int BCNT = (NT / 8) * KS * 64;  // u32 per B split slice
    constexpr int NWN  = NT / 16;
    constexpr int MT   = NWN;                 // m16-tiles per warp (= 128/(NWM*16))

    extern __shared__ __align__(16) char smem[];
    char* aH = smem;
    char* aL = smem + ASZ;
    uint32_t* sBh = (uint32_t*)(smem + 2 * ASZ);
    uint32_t* sBl = sBh + BCNT;

    int tid = threadIdx.x;
    int wid = tid >> 5, lane = tid & 31;
    int warpN = wid % NWN, warpM = wid / NWN;
    int rowBase = blockIdx.y * 128;
    int colBase = blockIdx.x * NT;

    // ---- stage B fragment slices ----
    {
        const uint4* srcH = (const uint4*)(BfH + (size_t)blockIdx.x * BCNT);
        const uint4* srcL = (const uint4*)(BfL + (size_t)blockIdx.x * BCNT);
        uint4* dH = (uint4*)sBh;
        uint4* dL = (uint4*)sBl;
        for (int i = tid; i < BCNT / 4; i += 256) {
            dH[i] = srcH[i];
            dL[i] = srcL[i];
        }
    }
    // ---- stage A: fp32 -> bf16 hi/lo, swizzled row-major ----
    {
        constexpr int CH = K / 8;             // 8-col chunks per row
        for (int t = tid; t < 128 * CH; t += 256) {
            int r = t / CH, c = t % CH;
            int k0 = c * 8;
            int row = rowBase + r;
            float4 v0 = make_float4(0.f, 0.f, 0.f, 0.f);
            float4 v1 = make_float4(0.f, 0.f, 0.f, 0.f);
            if (row < M) {
                const float* ap = A + (size_t)row * K + k0;
                v0 = *(const float4*)ap;
                v1 = *(const float4*)(ap + 4);
            }
            __nv_bfloat16 h[8]; float l[8];
            split_bf16(v0.x, h[0], l[0]); split_bf16(v0.y, h[1], l[1]);
            split_bf16(v0.z, h[2], l[2]); split_bf16(v0.w, h[3], l[3]);
            split_bf16(v1.x, h[4], l[4]); split_bf16(v1.y, h[5], l[5]);
            split_bf16(v1.z, h[6], l[6]); split_bf16(v1.w, h[7], l[7]);
            uint4 ph, pl;
            ph.x = pack_bf16(__bfloat162float(h[0]), __bfloat162float(h[1]));
            ph.y = pack_bf16(__bfloat162float(h[2]), __bfloat162float(h[3]));
            ph.z = pack_bf16(__bfloat162float(h[4]), __bfloat162float(h[5]));
            ph.w = pack_bf16(__bfloat162float(h[6]), __bfloat162float(h[7]));
            pl.x = pack_bf16(l[0], l[1]); pl.y = pack_bf16(l[2], l[3]);
            pl.z = pack_bf16(l[4], l[5]); pl.w = pack_bf16(l[6], l[7]);
            int off = r * ROWB + ((k0 * 2) ^ ((r & 7) << 4));
            *(uint4*)(aH + off) = ph;
            *(uint4*)(aL + off) = pl;
        }
    }
    __syncthreads();

    // ---- mainloop ----
    float acc[MT][2][4];
    #pragma unroll
    for (int mt = 0; mt < MT; mt++)
        #pragma unroll
        for (int nt = 0; nt < 2; nt++)
            #pragma unroll
            for (int j = 0; j < 4; j++) acc[mt][nt][j] = 0.0f;

    uint32_t aHb = smem_u32(aH);
    uint32_t aLb = smem_u32(aL);
    int lrow = lane & 15;                 // ldmatrix row within m16 tile
    int lkof = (lane >> 4) * 8;           // ldmatrix k offset (0 or 8)

    #pragma unroll
    for (int ks = 0; ks < KS; ks++) {
        uint2 bh[2], bl[2];
        #pragma unroll
        for (int nt = 0; nt < 2; nt++) {
            int ntl = warpN * 2 + nt;
            int off = ((ntl * KS + ks) * 32 + lane) * 2;
            bh[nt] = *(const uint2*)&sBh[off];
            bl[nt] = *(const uint2*)&sBl[off];
        }
        #pragma unroll
        for (int mt = 0; mt < MT; mt++) {
            int r = warpM * (MT * 16) + mt * 16 + lrow;
            int kb = ks * 16 + lkof;
            uint32_t off = (uint32_t)(r * ROWB + ((kb * 2) ^ ((r & 7) << 4)));
            uint32_t ah[4], al[4];
            ldm4(ah, aHb + off);
            ldm4(al, aLb + off);
            #pragma unroll
            for (int nt = 0; nt < 2; nt++) {
                mma_bf16(acc[mt][nt], ah, bh[nt]);
                mma_bf16(acc[mt][nt], ah, bl[nt]);
                mma_bf16(acc[mt][nt], al, bh[nt]);
            }
        }
    }

    // ---- epilogue ----
    #pragma unroll
    for (int mt = 0; mt < MT; mt++) {
        #pragma unroll
        for (int nt = 0; nt < 2; nt++) {
            int col = colBase + warpN * 16 + nt * 8 + (lane & 3) * 2;
            float2 bb = make_float2(0.f, 0.f);
            if (BIAS) bb = *(const float2*)&bias[col];
            int row0 = rowBase + warpM * (MT * 16) + mt * 16 + (lane >> 2);
            if (row0 < M) {
                float2 v = make_float2(acc[mt][nt][0] + bb.x, acc[mt][nt][1] + bb.y);
                if (RELU) { v.x = fmaxf(v.x, 0.f); v.y = fmaxf(v.y, 0.f); }
                *(float2*)&C[(size_t)row0 * Nout + col] = v;
            }
            int row1 = row0 + 8;
            if (row1 < M) {
                float2 v = make_float2(acc[mt][nt][2] + bb.x, acc[mt][nt][3] + bb.y);
                if (RELU) { v.x = fmaxf(v.x, 0.f); v.y = fmaxf(v.y, 0.f); }
                *(float2*)&C[(size_t)row1 * Nout + col] = v;
            }
        }
    }
}

// ---------------- aggregation (warp per node, padded weight buckets) ----------------
template <int D, bool BR>
__global__ __launch_bounds__(256) void k_agg(
        const float* __restrict__ t, const float* __restrict__ bias,
        float* __restrict__ out, int n) {
    constexpr int V = D / 32;
    int node = (blockIdx.x * blockDim.x + threadIdx.x) >> 5;
    int lane = threadIdx.x & 31;
    if (node >= n) return;

    float dn = g_dinv[node];
    int degR = (g_deg[node] + 3) & ~3;

    float acc[V];
    {
        const float* trow = t + (size_t)node * D + lane * V;
        float w = dn * dn;
        if constexpr (V == 4) {
            float4 a = *(const float4*)trow;
            acc[0] = w * a.x; acc[1] = w * a.y; acc[2] = w * a.z; acc[3] = w * a.w;
        } else {
            float2 a = *(const float2*)trow;
            acc[0] = w * a.x; acc[1] = w * a.y;
        }
    }

    const int*   bi = &g_csrc[(size_t)node * CAP];
    const float* bw = &g_wgt [(size_t)node * CAP];
    for (int e = 0; e < degR; e += 4) {
        int4   s4 = *(const int4*)&bi[e];
        float4 w4 = *(const float4*)&bw[e];
        const float* r0 = t + (size_t)s4.x * D + lane * V;
        const float* r1 = t + (size_t)s4.y * D + lane * V;
        const float* r2 = t + (size_t)s4.z * D + lane * V;
        const float* r3 = t + (size_t)s4.w * D + lane * V;
        if constexpr (V == 4) {
            float4 v0 = *(const float4*)r0;
            float4 v1 = *(const float4*)r1;
            float4 v2 = *(const float4*)r2;
            float4 v3 = *(const float4*)r3;
            acc[0] = fmaf(w4.x, v0.x, acc[0]); acc[1] = fmaf(w4.x, v0.y, acc[1]);
            acc[2] = fmaf(w4.x, v0.z, acc[2]); acc[3] = fmaf(w4.x, v0.w, acc[3]);
            acc[0] = fmaf(w4.y, v1.x, acc[0]); acc[1] = fmaf(w4.y, v1.y, acc[1]);
            acc[2] = fmaf(w4.y, v1.z, acc[2]); acc[3] = fmaf(w4.y, v1.w, acc[3]);
            acc[0] = fmaf(w4.z, v2.x, acc[0]); acc[1] = fmaf(w4.z, v2.y, acc[1]);
            acc[2] = fmaf(w4.z, v2.z, acc[2]); acc[3] = fmaf(w4.z, v2.w, acc[3]);
            acc[0] = fmaf(w4.w, v3.x, acc[0]); acc[1] = fmaf(w4.w, v3.y, acc[1]);
            acc[2] = fmaf(w4.w, v3.z, acc[2]); acc[3] = fmaf(w4.w, v3.w, acc[3]);
        } else {
            float2 v0 = *(const float2*)r0;
            float2 v1 = *(const float2*)r1;
            float2 v2 = *(const float2*)r2;
            float2 v3 = *(const float2*)r3;
            acc[0] = fmaf(w4.x, v0.x, acc[0]); acc[1] = fmaf(w4.x, v0.y, acc[1]);
            acc[0] = fmaf(w4.y, v1.x, acc[0]); acc[1] = fmaf(w4.y, v1.y, acc[1]);
            acc[0] = fmaf(w4.z, v2.x, acc[0]); acc[1] = fmaf(w4.z, v2.y, acc[1]);
            acc[0] = fmaf(w4.w, v3.x, acc[0]); acc[1] = fmaf(w4.w, v3.y, acc[1]);
        }
    }

    float* orow = out + (size_t)node * D + lane * V;
    if constexpr (V == 4) {
        float4 o;
        if (BR) {
            float4 bb = *(const float4*)&bias[lane * 4];
            o = make_float4(fmaxf(acc[0] + bb.x, 0.f), fmaxf(acc[1] + bb.y, 0.f),
                            fmaxf(acc[2] + bb.z, 0.f), fmaxf(acc[3] + bb.w, 0.f));
        } else {
            o = make_float4(acc[0], acc[1], acc[2], acc[3]);
        }
        *(float4*)orow = o;
    } else {
        float2 o;
        if (BR) {
            float2 bb = *(const float2*)&bias[lane * 2];
            o = make_float2(fmaxf(acc[0] + bb.x, 0.f), fmaxf(acc[1] + bb.y, 0.f));
        } else {
            o = make_float2(acc[0], acc[1]);
        }
        *(float2*)orow = o;
    }
}

// ---------------- launch ----------------
extern "C" void kernel_launch(void* const* d_in, const int* in_sizes, int n_in,
                              void* d_out, int out_size) {
    const float* x  = (const float*)d_in[0];
    const int*   ei = (const int*)d_in[1];
    const float* W1 = (const float*)d_in[3];
    const float* b1 = (const float*)d_in[4];
    const float* W2 = (const float*)d_in[5];
    const float* b2 = (const float*)d_in[6];
    const float* W3 = (const float*)d_in[7];
    const float* b3 = (const float*)d_in[8];
    const float* W4 = (const float*)d_in[9];
    const float* b4 = (const float*)d_in[10];
    const float* Wl = (const float*)d_in[11];
    const float* bl = (const float*)d_in[12];
    float* out = (float*)d_out;

    const int N = in_sizes[0] / 128;   // 40000
    const int E = in_sizes[1] / 2;     // 640000

    float *bufA, *bufB;
    uint32_t *bfH, *bfL;
    int* degP;
    cudaGetSymbolAddress((void**)&bufA, g_bufA);
    cudaGetSymbolAddress((void**)&bufB, g_bufB);
    cudaGetSymbolAddress((void**)&bfH, g_BfH);
    cudaGetSymbolAddress((void**)&bfL, g_BfL);
    cudaGetSymbolAddress((void**)&degP, g_deg);

    // dynamic smem: A(2*128*K*2) + B(NT*K*4)
    constexpr int SM_128_64 = 2 * 128 * 128 * 2 + 64 * 128 * 4;  // 98304
    constexpr int SM_64_64  = 2 * 128 * 64 * 2 + 64 * 64 * 4;    // 49152
    constexpr int SM_64_32  = 2 * 128 * 64 * 2 + 32 * 64 * 4;    // 40960
    cudaFuncSetAttribute(k_gemm_mma<128, 64, false, false>,
                         cudaFuncAttributeMaxDynamicSharedMemorySize, SM_128_64);
    cudaFuncSetAttribute(k_gemm_mma<64, 64, true, true>,
                         cudaFuncAttributeMaxDynamicSharedMemorySize, SM_64_64);
    cudaFuncSetAttribute(k_gemm_mma<64, 32, true, false>,
                         cudaFuncAttributeMaxDynamicSharedMemorySize, SM_64_32);

    // graph build
    cudaMemsetAsync(degP, 0, (size_t)N * sizeof(int));
    k_fill<<<(E + 255) / 256, 256>>>(ei, E);
    k_dinv<<<(N + 255) / 256, 256>>>(N);
    k_wgt<<<((size_t)N * CAP + 255) / 256, 256>>>(N);

    // B fragment images: offsets L1=0, L2=4096, L3=8192, L4=16384, L5=20480
    k_prepB<128, 64> <<<(2048 + 255) / 256, 256>>>(W1, bfH + 0,     bfL + 0);
    k_prepB<64, 128> <<<(2048 + 255) / 256, 256>>>(W2, bfH + 4096,  bfL + 4096);
    k_prepB<128, 128><<<(4096 + 255) / 256, 256>>>(W3, bfH + 8192,  bfL + 8192);
    k_prepB<128, 64> <<<(2048 + 255) / 256, 256>>>(W4, bfH + 16384, bfL + 16384);
    k_prepB<64, 32>  <<<(512 + 255) / 256, 256>>>(Wl, bfH + 20480, bfL + 20480);

    const int aggBlocks = (N + 7) / 8;
    const int gy = (N + 127) / 128;

    // L1: t1 = x @ W1 -> bufA ; a1 = relu(agg(t1)+b1) -> bufB
    k_gemm_mma<128, 64, false, false><<<dim3(1, gy), 256, SM_128_64>>>(
        x, bfH + 0, bfL + 0, nullptr, bufA, N, 64);
    k_agg<64, true><<<aggBlocks, 256>>>(bufA, b1, bufB, N);

    // L2 (agg-first): u = agg(a1) -> bufA ; a2 = relu(u @ W2 + b2) -> bufB
    k_agg<64, false><<<aggBlocks, 256>>>(bufB, nullptr, bufA, N);
    k_gemm_mma<64, 64, true, true><<<dim3(2, gy), 256, SM_64_64>>>(
        bufA, bfH + 4096, bfL + 4096, b2, bufB, N, 128);

    // L3: t3 = a2 @ W3 -> bufA ; a3 = relu(agg(t3)+b3) -> bufB
    k_gemm_mma<128, 64, false, false><<<dim3(2, gy), 256, SM_128_64>>>(
        bufB, bfH + 8192, bfL + 8192, nullptr, bufA, N, 128);
    k_agg<128, true><<<aggBlocks, 256>>>(bufA, b3, bufB, N);

    // L4: t4 = a3 @ W4 -> bufA ; a4 = relu(agg(t4)+b4) -> bufB
    k_gemm_mma<128, 64, false, false><<<dim3(1, gy), 256, SM_128_64>>>(
        bufB, bfH + 16384, bfL + 16384, nullptr, bufA, N, 64);
    k_agg<64, true><<<aggBlocks, 256>>>(bufA, b4, bufB, N);

    // L5: out = a4 @ Wl + bl
    k_gemm_mma<64, 32, true, false><<<dim3(1, gy), 256, SM_64_32>>>(
        bufB, bfH + 20480, bfL + 20480, bl, out, N, 32);
}

// round 7
// speedup vs baseline: 1.5311x; 1.5311x over previous
#include <cuda_runtime.h>
#include <cuda_bf16.h>
#include <cstdint>

#define MAXN 40000
#define CAP  96

// ---------------- device scratch ----------------
__device__ int   g_deg[MAXN];
__device__ int   g_csrc[(size_t)MAXN * CAP];
__device__ float g_wgt [(size_t)MAXN * CAP];
__device__ float g_bufA[(size_t)MAXN * 128];
__device__ float g_bufB[(size_t)MAXN * 64];
__device__ __nv_bfloat16 g_hi0[(size_t)MAXN * 128];
__device__ __nv_bfloat16 g_lo0[(size_t)MAXN * 128];
__device__ __nv_bfloat16 g_hi1[(size_t)MAXN * 128];
__device__ __nv_bfloat16 g_lo1[(size_t)MAXN * 128];
// B fragment images (hi/lo), mma.sync B-register order
// u32 offsets: L1=0, L2=4096, L3=8192, L4=16384, L5=20480
__device__ uint32_t g_BfH[21504];
__device__ uint32_t g_BfL[21504];

// ---------------- helpers ----------------
__device__ __forceinline__ uint32_t smem_u32(const void* p) {
    uint32_t a;
    asm("{ .reg .u64 t; cvta.to.shared.u64 t, %1; cvt.u32.u64 %0, t; }"
        : "=r"(a) : "l"(p));
    return a;
}
__device__ __forceinline__ uint32_t pack_bf16(float x, float y) {
    __nv_bfloat162 p = __floats2bfloat162_rn(x, y);
    return *(uint32_t*)&p;
}
__device__ __forceinline__ void split_bf16(float v, __nv_bfloat16& h, float& lo) {
    h = __float2bfloat16_rn(v);
    lo = v - __bfloat162float(h);
}
__device__ __forceinline__ void ldm4(uint32_t* a, uint32_t addr) {
    asm volatile("ldmatrix.sync.aligned.m8n8.x4.shared.b16 {%0,%1,%2,%3}, [%4];"
                 : "=r"(a[0]), "=r"(a[1]), "=r"(a[2]), "=r"(a[3]) : "r"(addr));
}
__device__ __forceinline__ void mma_bf16(float* d, const uint32_t* a, uint2 b) {
    asm volatile("mma.sync.aligned.m16n8k16.row.col.f32.bf16.bf16.f32 "
                 "{%0,%1,%2,%3}, {%4,%5,%6,%7}, {%8,%9}, {%0,%1,%2,%3};"
                 : "+f"(d[0]), "+f"(d[1]), "+f"(d[2]), "+f"(d[3])
                 : "r"(a[0]), "r"(a[1]), "r"(a[2]), "r"(a[3]),
                   "r"(b.x), "r"(b.y));
}

// ---------------- graph build ----------------
__global__ void k_fill(const int* __restrict__ ei, int E) {
    int e = blockIdx.x * blockDim.x + threadIdx.x;
    if (e < E) {
        int d = ei[E + e];
        int s = ei[e];
        int pos = atomicAdd(&g_deg[d], 1);
        g_csrc[(size_t)d * CAP + pos] = s;
    }
}
// weight per slot (dinv inline); pad bucket to multiple of 4
__global__ void k_wgt(int n) {
    int idx = blockIdx.x * blockDim.x + threadIdx.x;
    int node = idx / CAP;
    int slot = idx - node * CAP;
    if (node >= n) return;
    int deg = g_deg[node];
    int degR = (deg + 3) & ~3;
    if (slot >= degR) return;
    size_t p = (size_t)node * CAP + slot;
    if (slot < deg) {
        int s = g_csrc[p];
        g_wgt[p] = rsqrtf((float)deg + 1.0f) * rsqrtf((float)g_deg[s] + 1.0f);
    } else {
        g_csrc[p] = node;
        g_wgt[p] = 0.0f;
    }
}

// ---------------- one-shot weight fragment prep for ALL layers ----------------
__device__ __forceinline__ void prep_one(const float* __restrict__ W, int K,
                                         int NOUT, int base, int off) {
    int KS = K / 16;
    int lane = off & 31, rest = off >> 5;
    int ks = rest % KS, nt = rest / KS;
    int n  = nt * 8 + (lane >> 2);
    int k0 = ks * 16 + (lane & 3) * 2;
    float v00 = W[(size_t)(k0 + 0) * NOUT + n];
    float v01 = W[(size_t)(k0 + 1) * NOUT + n];
    float v10 = W[(size_t)(k0 + 8) * NOUT + n];
    float v11 = W[(size_t)(k0 + 9) * NOUT + n];
    __nv_bfloat16 h00, h01, h10, h11;
    float l00, l01, l10, l11;
    split_bf16(v00, h00, l00); split_bf16(v01, h01, l01);
    split_bf16(v10, h10, l10); split_bf16(v11, h11, l11);
    int o = base + off * 2;
    g_BfH[o + 0] = pack_bf16(__bfloat162float(h00), __bfloat162float(h01));
    g_BfH[o + 1] = pack_bf16(__bfloat162float(h10), __bfloat162float(h11));
    g_BfL[o + 0] = pack_bf16(l00, l01);
    g_BfL[o + 1] = pack_bf16(l10, l11);
}
__global__ void k_prepAll(const float* __restrict__ W1, const float* __restrict__ W2,
                          const float* __restrict__ W3, const float* __restrict__ W4,
                          const float* __restrict__ Wl) {
    int idx = blockIdx.x * blockDim.x + threadIdx.x;
    if (idx < 2048)       prep_one(W1, 128, 64,  0,     idx);
    else if (idx < 4096)  prep_one(W2, 64,  128, 4096,  idx - 2048);
    else if (idx < 8192)  prep_one(W3, 128, 128, 8192,  idx - 4096);
    else if (idx < 10240) prep_one(W4, 128, 64,  16384, idx - 8192);
    else if (idx < 10752) prep_one(Wl, 64,  32,  20480, idx - 10240);
}

// ---------------- x -> bf16 hi/lo images ----------------
__global__ void k_convX(const float* __restrict__ x, __nv_bfloat16* __restrict__ hi,
                        __nv_bfloat16* __restrict__ lo, int total4) {
    int i = blockIdx.x * blockDim.x + threadIdx.x;
    if (i >= total4) return;
    float4 v = ((const float4*)x)[i];
    __nv_bfloat16 h0, h1, h2, h3; float l0, l1, l2, l3;
    split_bf16(v.x, h0, l0); split_bf16(v.y, h1, l1);
    split_bf16(v.z, h2, l2); split_bf16(v.w, h3, l3);
    uint2 ph, pl;
    ph.x = pack_bf16(__bfloat162float(h0), __bfloat162float(h1));
    ph.y = pack_bf16(__bfloat162float(h2), __bfloat162float(h3));
    pl.x = pack_bf16(l0, l1); pl.y = pack_bf16(l2, l3);
    *(uint2*)&hi[(size_t)i * 4] = ph;
    *(uint2*)&lo[(size_t)i * 4] = pl;
}

// ---------------- tensor-core GEMM (3-term bf16 split, bf16 inputs) ----------------
// CTA tile 128 x NT, 8 warps. A hi/lo images staged to smem; B frags from gmem.
template <int K, int NT, bool BIAS, bool RELU, bool OUTBF>
__global__ __launch_bounds__(256) void k_gemm_mma(
        const __nv_bfloat16* __restrict__ Ahi, const __nv_bfloat16* __restrict__ Alo,
        const uint32_t* __restrict__ BfH, const uint32_t* __restrict__ BfL,
        const float* __restrict__ bias, float* __restrict__ C,
        __nv_bfloat16* __restrict__ Chi, __nv_bfloat16* __restrict__ Clo,
        int M, int Nout) {
    constexpr int KS   = K / 16;
    constexpr int ROWB = K * 2;
    constexpr int ASZ  = 128 * K * 2;
    constexpr int BCNT = (NT / 8) * KS * 64;
    constexpr int NWN  = NT / 16;
    constexpr int MT   = NWN;

    extern __shared__ __align__(16) char smem[];
    char* aH = smem;
    char* aL = smem + ASZ;

    int tid = threadIdx.x;
    int wid = tid >> 5, lane = tid & 31;
    int warpN = wid % NWN, warpM = wid / NWN;
    int rowBase = blockIdx.y * 128;
    int colBase = blockIdx.x * NT;

    // ---- stage A (copy-only, swizzled; 16B = 8 bf16 per chunk) ----
    {
        constexpr int CH = K / 8;
        for (int t = tid; t < 128 * CH; t += 256) {
            int r = t / CH, c = t % CH;
            int row = rowBase + r;
            uint4 vh = make_uint4(0u, 0u, 0u, 0u);
            uint4 vl = make_uint4(0u, 0u, 0u, 0u);
            if (row < M) {
                vh = *(const uint4*)&Ahi[(size_t)row * K + c * 8];
                vl = *(const uint4*)&Alo[(size_t)row * K + c * 8];
            }
            int off = r * ROWB + ((c * 16) ^ ((r & 7) << 4));
            *(uint4*)(aH + off) = vh;
            *(uint4*)(aL + off) = vl;
        }
    }
    __syncthreads();

    float acc[MT][2][4];
    #pragma unroll
    for (int mt = 0; mt < MT; mt++)
        #pragma unroll
        for (int nt = 0; nt < 2; nt++)
            #pragma unroll
            for (int j = 0; j < 4; j++) acc[mt][nt][j] = 0.0f;

    const uint32_t* pBh = BfH + (size_t)blockIdx.x * BCNT;
    const uint32_t* pBl = BfL + (size_t)blockIdx.x * BCNT;
    uint32_t aHb = smem_u32(aH);
    uint32_t aLb = smem_u32(aL);
    int lrow = lane & 15;
    int lkof = (lane >> 4) * 8;

    #pragma unroll
    for (int ks = 0; ks < KS; ks++) {
        uint2 bh[2], bl[2];
        #pragma unroll
        for (int nt = 0; nt < 2; nt++) {
            int ntl = warpN * 2 + nt;
            int off = ((ntl * KS + ks) * 32 + lane) * 2;
            bh[nt] = *(const uint2*)&pBh[off];
            bl[nt] = *(const uint2*)&pBl[off];
        }
        #pragma unroll
        for (int mt = 0; mt < MT; mt++) {
            int r = warpM * (MT * 16) + mt * 16 + lrow;
            int kb = ks * 16 + lkof;
            uint32_t off = (uint32_t)(r * ROWB + ((kb * 2) ^ ((r & 7) << 4)));
            uint32_t ah[4], al[4];
            ldm4(ah, aHb + off);
            ldm4(al, aLb + off);
            #pragma unroll
            for (int nt = 0; nt < 2; nt++) {
                mma_bf16(acc[mt][nt], ah, bh[nt]);
                mma_bf16(acc[mt][nt], ah, bl[nt]);
                mma_bf16(acc[mt][nt], al, bh[nt]);
            }
        }
    }

    // ---- epilogue ----
    #pragma unroll
    for (int mt = 0; mt < MT; mt++) {
        #pragma unroll
        for (int nt = 0; nt < 2; nt++) {
            int col = colBase + warpN * 16 + nt * 8 + (lane & 3) * 2;
            float2 bb = make_float2(0.f, 0.f);
            if (BIAS) bb = *(const float2*)&bias[col];
            #pragma unroll
            for (int half = 0; half < 2; half++) {
                int row = rowBase + warpM * (MT * 16) + mt * 16 + (lane >> 2) + half * 8;
                if (row < M) {
                    float vx = acc[mt][nt][half * 2 + 0] + bb.x;
                    float vy = acc[mt][nt][half * 2 + 1] + bb.y;
                    if (RELU) { vx = fmaxf(vx, 0.f); vy = fmaxf(vy, 0.f); }
                    if (OUTBF) {
                        __nv_bfloat16 hx, hy; float lx, ly;
                        split_bf16(vx, hx, lx);
                        split_bf16(vy, hy, ly);
                        uint32_t ph = pack_bf16(__bfloat162float(hx), __bfloat162float(hy));
                        uint32_t pl = pack_bf16(lx, ly);
                        *(uint32_t*)&Chi[(size_t)row * Nout + col] = ph;
                        *(uint32_t*)&Clo[(size_t)row * Nout + col] = pl;
                    } else {
                        *(float2*)&C[(size_t)row * Nout + col] = make_float2(vx, vy);
                    }
                }
            }
        }
    }
}

// ---------------- aggregation (warp per node) ----------------
template <int D, bool BR, bool OUTBF>
__global__ __launch_bounds__(256) void k_agg(
        const float* __restrict__ t, const float* __restrict__ bias,
        float* __restrict__ outF, __nv_bfloat16* __restrict__ outHi,
        __nv_bfloat16* __restrict__ outLo, int n) {
    constexpr int V = D / 32;
    int node = (blockIdx.x * blockDim.x + threadIdx.x) >> 5;
    int lane = threadIdx.x & 31;
    if (node >= n) return;

    int deg = g_deg[node];
    float dn = rsqrtf((float)deg + 1.0f);
    int degR = (deg + 3) & ~3;

    float acc[V];
    {
        const float* trow = t + (size_t)node * D + lane * V;
        float w = dn * dn;
        if constexpr (V == 4) {
            float4 a = *(const float4*)trow;
            acc[0] = w * a.x; acc[1] = w * a.y; acc[2] = w * a.z; acc[3] = w * a.w;
        } else {
            float2 a = *(const float2*)trow;
            acc[0] = w * a.x; acc[1] = w * a.y;
        }
    }

    const int*   bi = &g_csrc[(size_t)node * CAP];
    const float* bw = &g_wgt [(size_t)node * CAP];
    for (int e = 0; e < degR; e += 4) {
        int4   s4 = *(const int4*)&bi[e];
        float4 w4 = *(const float4*)&bw[e];
        const float* r0 = t + (size_t)s4.x * D + lane * V;
        const float* r1 = t + (size_t)s4.y * D + lane * V;
        const float* r2 = t + (size_t)s4.z * D + lane * V;
        const float* r3 = t + (size_t)s4.w * D + lane * V;
        if constexpr (V == 4) {
            float4 v0 = *(const float4*)r0;
            float4 v1 = *(const float4*)r1;
            float4 v2 = *(const float4*)r2;
            float4 v3 = *(const float4*)r3;
            acc[0] = fmaf(w4.x, v0.x, acc[0]); acc[1] = fmaf(w4.x, v0.y, acc[1]);
            acc[2] = fmaf(w4.x, v0.z, acc[2]); acc[3] = fmaf(w4.x, v0.w, acc[3]);
            acc[0] = fmaf(w4.y, v1.x, acc[0]); acc[1] = fmaf(w4.y, v1.y, acc[1]);
            acc[2] = fmaf(w4.y, v1.z, acc[2]); acc[3] = fmaf(w4.y, v1.w, acc[3]);
            acc[0] = fmaf(w4.z, v2.x, acc[0]); acc[1] = fmaf(w4.z, v2.y, acc[1]);
            acc[2] = fmaf(w4.z, v2.z, acc[2]); acc[3] = fmaf(w4.z, v2.w, acc[3]);
            acc[0] = fmaf(w4.w, v3.x, acc[0]); acc[1] = fmaf(w4.w, v3.y, acc[1]);
            acc[2] = fmaf(w4.w, v3.z, acc[2]); acc[3] = fmaf(w4.w, v3.w, acc[3]);
        } else {
            float2 v0 = *(const float2*)r0;
            float2 v1 = *(const float2*)r1;
            float2 v2 = *(const float2*)r2;
            float2 v3 = *(const float2*)r3;
            acc[0] = fmaf(w4.x, v0.x, acc[0]); acc[1] = fmaf(w4.x, v0.y, acc[1]);
            acc[0] = fmaf(w4.y, v1.x, acc[0]); acc[1] = fmaf(w4.y, v1.y, acc[1]);
            acc[0] = fmaf(w4.z, v2.x, acc[0]); acc[1] = fmaf(w4.z, v2.y, acc[1]);
            acc[0] = fmaf(w4.w, v3.x, acc[0]); acc[1] = fmaf(w4.w, v3.y, acc[1]);
        }
    }

    // epilogue
    float v[V];
    #pragma unroll
    for (int j = 0; j < V; j++) {
        float b = BR ? bias[lane * V + j] : 0.0f;
        float r = acc[j] + b;
        v[j] = BR ? fmaxf(r, 0.0f) : r;
    }
    if constexpr (OUTBF) {
        __nv_bfloat16 h[V]; float l[V];
        #pragma unroll
        for (int j = 0; j < V; j++) split_bf16(v[j], h[j], l[j]);
        if constexpr (V == 4) {
            uint2 ph, pl;
            ph.x = pack_bf16(__bfloat162float(h[0]), __bfloat162float(h[1]));
            ph.y = pack_bf16(__bfloat162float(h[2]), __bfloat162float(h[3]));
            pl.x = pack_bf16(l[0], l[1]); pl.y = pack_bf16(l[2], l[3]);
            *(uint2*)&outHi[(size_t)node * D + lane * 4] = ph;
            *(uint2*)&outLo[(size_t)node * D + lane * 4] = pl;
        } else {
            *(uint32_t*)&outHi[(size_t)node * D + lane * 2] =
                pack_bf16(__bfloat162float(h[0]), __bfloat162float(h[1]));
            *(uint32_t*)&outLo[(size_t)node * D + lane * 2] = pack_bf16(l[0], l[1]);
        }
    } else {
        if constexpr (V == 4)
            *(float4*)&outF[(size_t)node * D + lane * 4] =
                make_float4(v[0], v[1], v[2], v[3]);
        else
            *(float2*)&outF[(size_t)node * D + lane * 2] = make_float2(v[0], v[1]);
    }
}

// ---------------- launch ----------------
extern "C" void kernel_launch(void* const* d_in, const int* in_sizes, int n_in,
                              void* d_out, int out_size) {
    const float* x  = (const float*)d_in[0];
    const int*   ei = (const int*)d_in[1];
    const float* W1 = (const float*)d_in[3];
    const float* b1 = (const float*)d_in[4];
    const float* W2 = (const float*)d_in[5];
    const float* b2 = (const float*)d_in[6];
    const float* W3 = (const float*)d_in[7];
    const float* b3 = (const float*)d_in[8];
    const float* W4 = (const float*)d_in[9];
    const float* b4 = (const float*)d_in[10];
    const float* Wl = (const float*)d_in[11];
    const float* bl = (const float*)d_in[12];
    float* out = (float*)d_out;

    const int N = in_sizes[0] / 128;   // 40000
    const int E = in_sizes[1] / 2;     // 640000

    float *bufA, *bufB;
    __nv_bfloat16 *hi0, *lo0, *hi1, *lo1;
    uint32_t *bfH, *bfL;
    int* degP;
    cudaGetSymbolAddress((void**)&bufA, g_bufA);
    cudaGetSymbolAddress((void**)&bufB, g_bufB);
    cudaGetSymbolAddress((void**)&hi0, g_hi0);
    cudaGetSymbolAddress((void**)&lo0, g_lo0);
    cudaGetSymbolAddress((void**)&hi1, g_hi1);
    cudaGetSymbolAddress((void**)&lo1, g_lo1);
    cudaGetSymbolAddress((void**)&bfH, g_BfH);
    cudaGetSymbolAddress((void**)&bfL, g_BfL);
    cudaGetSymbolAddress((void**)&degP, g_deg);

    constexpr int SM_K128 = 2 * 128 * 128 * 2;   // 65536
    constexpr int SM_K64  = 2 * 128 * 64 * 2;    // 32768
    cudaFuncSetAttribute(k_gemm_mma<128, 64, false, false, false>,
                         cudaFuncAttributeMaxDynamicSharedMemorySize, SM_K128);
    cudaFuncSetAttribute(k_gemm_mma<64, 64, true, true, true>,
                         cudaFuncAttributeMaxDynamicSharedMemorySize, SM_K64);
    cudaFuncSetAttribute(k_gemm_mma<64, 32, true, false, false>,
                         cudaFuncAttributeMaxDynamicSharedMemorySize, SM_K64);

    // graph build + one-shot preps
    cudaMemsetAsync(degP, 0, (size_t)N * sizeof(int));
    k_fill<<<(E + 255) / 256, 256>>>(ei, E);
    k_wgt<<<((size_t)N * CAP + 255) / 256, 256>>>(N);
    k_prepAll<<<(10752 + 255) / 256, 256>>>(W1, W2, W3, W4, Wl);
    k_convX<<<(N * 32 + 255) / 256, 256>>>(x, hi0, lo0, N * 32);

    const int aggBlocks = (N + 7) / 8;
    const int gy = (N + 127) / 128;

    // L1: t1 = x @ W1 -> bufA(f32); a1 = relu(agg(t1)+b1) -> bufB(f32)
    k_gemm_mma<128, 64, false, false, false><<<dim3(1, gy), 256, SM_K128>>>(
        hi0, lo0, bfH + 0, bfL + 0, nullptr, bufA, nullptr, nullptr, N, 64);
    k_agg<64, true, false><<<aggBlocks, 256>>>(bufA, b1, bufB, nullptr, nullptr, N);

    // L2 (agg-first): u = agg(a1) -> hi0/lo0 ; a2 = relu(u@W2+b2) -> hi1/lo1
    k_agg<64, false, true><<<aggBlocks, 256>>>(bufB, nullptr, nullptr, hi0, lo0, N);
    k_gemm_mma<64, 64, true, true, true><<<dim3(2, gy), 256, SM_K64>>>(
        hi0, lo0, bfH + 4096, bfL + 4096, b2, nullptr, hi1, lo1, N, 128);

    // L3: t3 = a2 @ W3 -> bufA(f32); a3 = relu(agg+b3) -> hi0/lo0
    k_gemm_mma<128, 64, false, false, false><<<dim3(2, gy), 256, SM_K128>>>(
        hi1, lo1, bfH + 8192, bfL + 8192, nullptr, bufA, nullptr, nullptr, N, 128);
    k_agg<128, true, true><<<aggBlocks, 256>>>(bufA, b3, nullptr, hi0, lo0, N);

    // L4: t4 = a3 @ W4 -> bufA(f32); a4 = relu(agg+b4) -> hi1/lo1
    k_gemm_mma<128, 64, false, false, false><<<dim3(1, gy), 256, SM_K128>>>(
        hi0, lo0, bfH + 16384, bfL + 16384, nullptr, bufA, nullptr, nullptr, N, 64);
    k_agg<64, true, true><<<aggBlocks, 256>>>(bufA, b4, nullptr, hi1, lo1, N);

    // L5: out = a4 @ Wl + bl
    k_gemm_mma<64, 32, true, false, false><<<dim3(1, gy), 256, SM_K64>>>(
        hi1, lo1, bfH + 20480, bfL + 20480, bl, out, nullptr, nullptr, N, 32);
}

// round 8
// speedup vs baseline: 1.6455x; 1.0747x over previous
#include <cuda_runtime.h>
#include <cuda_bf16.h>
#include <cstdint>

#define MAXN 40000
#define CAP  96

// ---------------- device scratch ----------------
__device__ int   g_deg[MAXN];
__device__ int   g_csrc[(size_t)MAXN * CAP];
__device__ float g_wgt [(size_t)MAXN * CAP];
__device__ float g_bufA[(size_t)MAXN * 128];
__device__ float g_bufB[(size_t)MAXN * 64];
__device__ __nv_bfloat16 g_hi0[(size_t)MAXN * 128];
__device__ __nv_bfloat16 g_lo0[(size_t)MAXN * 128];
__device__ __nv_bfloat16 g_hi1[(size_t)MAXN * 128];
__device__ __nv_bfloat16 g_lo1[(size_t)MAXN * 128];
// B fragment images (hi/lo), mma.sync B-register order
// u32 offsets: L1=0, L2=4096, L3=8192, L4=16384, L5=20480
__device__ uint32_t g_BfH[21504];
__device__ uint32_t g_BfL[21504];

// ---------------- helpers ----------------
__device__ __forceinline__ uint32_t smem_u32(const void* p) {
    uint32_t a;
    asm("{ .reg .u64 t; cvta.to.shared.u64 t, %1; cvt.u32.u64 %0, t; }"
        : "=r"(a) : "l"(p));
    return a;
}
__device__ __forceinline__ uint32_t pack_bf16(float x, float y) {
    __nv_bfloat162 p = __floats2bfloat162_rn(x, y);
    return *(uint32_t*)&p;
}
__device__ __forceinline__ void split_bf16(float v, __nv_bfloat16& h, float& lo) {
    h = __float2bfloat16_rn(v);
    lo = v - __bfloat162float(h);
}
__device__ __forceinline__ void ldm4(uint32_t* a, uint32_t addr) {
    asm volatile("ldmatrix.sync.aligned.m8n8.x4.shared.b16 {%0,%1,%2,%3}, [%4];"
                 : "=r"(a[0]), "=r"(a[1]), "=r"(a[2]), "=r"(a[3]) : "r"(addr));
}
__device__ __forceinline__ void mma_bf16(float* d, const uint32_t* a, uint2 b) {
    asm volatile("mma.sync.aligned.m16n8k16.row.col.f32.bf16.bf16.f32 "
                 "{%0,%1,%2,%3}, {%4,%5,%6,%7}, {%8,%9}, {%0,%1,%2,%3};"
                 : "+f"(d[0]), "+f"(d[1]), "+f"(d[2]), "+f"(d[3])
                 : "r"(a[0]), "r"(a[1]), "r"(a[2]), "r"(a[3]),
                   "r"(b.x), "r"(b.y));
}

// ---------------- graph build ----------------
__global__ void k_fill(const int* __restrict__ ei, int E) {
    int e = blockIdx.x * blockDim.x + threadIdx.x;
    if (e < E) {
        int d = ei[E + e];
        int s = ei[e];
        int pos = atomicAdd(&g_deg[d], 1);
        g_csrc[(size_t)d * CAP + pos] = s;
    }
}
// weight per slot (dinv inline); pad bucket to multiple of 4
__global__ void k_wgt(int n) {
    int idx = blockIdx.x * blockDim.x + threadIdx.x;
    int node = idx / CAP;
    int slot = idx - node * CAP;
    if (node >= n) return;
    int deg = g_deg[node];
    int degR = (deg + 3) & ~3;
    if (slot >= degR) return;
    size_t p = (size_t)node * CAP + slot;
    if (slot < deg) {
        int s = g_csrc[p];
        g_wgt[p] = rsqrtf((float)deg + 1.0f) * rsqrtf((float)g_deg[s] + 1.0f);
    } else {
        g_csrc[p] = node;
        g_wgt[p] = 0.0f;
    }
}

// ---------------- one-shot weight fragment prep for ALL layers ----------------
__device__ __forceinline__ void prep_one(const float* __restrict__ W, int K,
                                         int NOUT, int base, int off) {
    int KS = K / 16;
    int lane = off & 31, rest = off >> 5;
    int ks = rest % KS, nt = rest / KS;
    int n  = nt * 8 + (lane >> 2);
    int k0 = ks * 16 + (lane & 3) * 2;
    float v00 = W[(size_t)(k0 + 0) * NOUT + n];
    float v01 = W[(size_t)(k0 + 1) * NOUT + n];
    float v10 = W[(size_t)(k0 + 8) * NOUT + n];
    float v11 = W[(size_t)(k0 + 9) * NOUT + n];
    __nv_bfloat16 h00, h01, h10, h11;
    float l00, l01, l10, l11;
    split_bf16(v00, h00, l00); split_bf16(v01, h01, l01);
    split_bf16(v10, h10, l10); split_bf16(v11, h11, l11);
    int o = base + off * 2;
    g_BfH[o + 0] = pack_bf16(__bfloat162float(h00), __bfloat162float(h01));
    g_BfH[o + 1] = pack_bf16(__bfloat162float(h10), __bfloat162float(h11));
    g_BfL[o + 0] = pack_bf16(l00, l01);
    g_BfL[o + 1] = pack_bf16(l10, l11);
}
__global__ void k_prepAll(const float* __restrict__ W1, const float* __restrict__ W2,
                          const float* __restrict__ W3, const float* __restrict__ W4,
                          const float* __restrict__ Wl) {
    int idx = blockIdx.x * blockDim.x + threadIdx.x;
    if (idx < 2048)       prep_one(W1, 128, 64,  0,     idx);
    else if (idx < 4096)  prep_one(W2, 64,  128, 4096,  idx - 2048);
    else if (idx < 8192)  prep_one(W3, 128, 128, 8192,  idx - 4096);
    else if (idx < 10240) prep_one(W4, 128, 64,  16384, idx - 8192);
    else if (idx < 10752) prep_one(Wl, 64,  32,  20480, idx - 10240);
}

// ---------------- tensor-core GEMM (3-term bf16 split) ----------------
// CTA tile 128 x NT, 8 warps. A staged to smem (bf16 hi/lo images, or fp32
// with inline split when INF32). B frags streamed from gmem/L2.
template <int K, int NT, bool BIAS, bool RELU, bool OUTBF, bool INF32>
__global__ __launch_bounds__(256) void k_gemm_mma(
        const __nv_bfloat16* __restrict__ Ahi, const __nv_bfloat16* __restrict__ Alo,
        const float* __restrict__ Af,
        const uint32_t* __restrict__ BfH, const uint32_t* __restrict__ BfL,
        const float* __restrict__ bias, float* __restrict__ C,
        __nv_bfloat16* __restrict__ Chi, __nv_bfloat16* __restrict__ Clo,
        int M, int Nout) {
    constexpr int KS   = K / 16;
    constexpr int ROWB = K * 2;
    constexpr int ASZ  = 128 * K * 2;
    constexpr int BCNT = (NT / 8) * KS * 64;
    constexpr int NWN  = NT / 16;
    constexpr int MT   = NWN;

    extern __shared__ __align__(16) char smem[];
    char* aH = smem;
    char* aL = smem + ASZ;

    int tid = threadIdx.x;
    int wid = tid >> 5, lane = tid & 31;
    int warpN = wid % NWN, warpM = wid / NWN;
    int rowBase = blockIdx.y * 128;
    int colBase = blockIdx.x * NT;

    // ---- stage A (swizzled; 16B = 8 bf16 per chunk) ----
    {
        constexpr int CH = K / 8;
        for (int t = tid; t < 128 * CH; t += 256) {
            int r = t / CH, c = t % CH;
            int row = rowBase + r;
            uint4 vh = make_uint4(0u, 0u, 0u, 0u);
            uint4 vl = make_uint4(0u, 0u, 0u, 0u);
            if (row < M) {
                if constexpr (INF32) {
                    const float* ap = Af + (size_t)row * K + c * 8;
                    float4 v0 = *(const float4*)ap;
                    float4 v1 = *(const float4*)(ap + 4);
                    __nv_bfloat16 h[8]; float l[8];
                    split_bf16(v0.x, h[0], l[0]); split_bf16(v0.y, h[1], l[1]);
                    split_bf16(v0.z, h[2], l[2]); split_bf16(v0.w, h[3], l[3]);
                    split_bf16(v1.x, h[4], l[4]); split_bf16(v1.y, h[5], l[5]);
                    split_bf16(v1.z, h[6], l[6]); split_bf16(v1.w, h[7], l[7]);
                    vh.x = pack_bf16(__bfloat162float(h[0]), __bfloat162float(h[1]));
                    vh.y = pack_bf16(__bfloat162float(h[2]), __bfloat162float(h[3]));
                    vh.z = pack_bf16(__bfloat162float(h[4]), __bfloat162float(h[5]));
                    vh.w = pack_bf16(__bfloat162float(h[6]), __bfloat162float(h[7]));
                    vl.x = pack_bf16(l[0], l[1]); vl.y = pack_bf16(l[2], l[3]);
                    vl.z = pack_bf16(l[4], l[5]); vl.w = pack_bf16(l[6], l[7]);
                } else {
                    vh = *(const uint4*)&Ahi[(size_t)row * K + c * 8];
                    vl = *(const uint4*)&Alo[(size_t)row * K + c * 8];
                }
            }
            int off = r * ROWB + ((c * 16) ^ ((r & 7) << 4));
            *(uint4*)(aH + off) = vh;
            *(uint4*)(aL + off) = vl;
        }
    }
    __syncthreads();

    float acc[MT][2][4];
    #pragma unroll
    for (int mt = 0; mt < MT; mt++)
        #pragma unroll
        for (int nt = 0; nt < 2; nt++)
            #pragma unroll
            for (int j = 0; j < 4; j++) acc[mt][nt][j] = 0.0f;

    const uint32_t* pBh = BfH + (size_t)blockIdx.x * BCNT;
    const uint32_t* pBl = BfL + (size_t)blockIdx.x * BCNT;
    uint32_t aHb = smem_u32(aH);
    uint32_t aLb = smem_u32(aL);
    int lrow = lane & 15;
    int lkof = (lane >> 4) * 8;

    #pragma unroll
    for (int ks = 0; ks < KS; ks++) {
        uint2 bh[2], bl[2];
        #pragma unroll
        for (int nt = 0; nt < 2; nt++) {
            int ntl = warpN * 2 + nt;
            int off = ((ntl * KS + ks) * 32 + lane) * 2;
            bh[nt] = *(const uint2*)&pBh[off];
            bl[nt] = *(const uint2*)&pBl[off];
        }
        #pragma unroll
        for (int mt = 0; mt < MT; mt++) {
            int r = warpM * (MT * 16) + mt * 16 + lrow;
            int kb = ks * 16 + lkof;
            uint32_t off = (uint32_t)(r * ROWB + ((kb * 2) ^ ((r & 7) << 4)));
            uint32_t ah[4], al[4];
            ldm4(ah, aHb + off);
            ldm4(al, aLb + off);
            #pragma unroll
            for (int nt = 0; nt < 2; nt++) {
                mma_bf16(acc[mt][nt], ah, bh[nt]);
                mma_bf16(acc[mt][nt], ah, bl[nt]);
                mma_bf16(acc[mt][nt], al, bh[nt]);
            }
        }
    }

    // ---- epilogue ----
    #pragma unroll
    for (int mt = 0; mt < MT; mt++) {
        #pragma unroll
        for (int nt = 0; nt < 2; nt++) {
            int col = colBase + warpN * 16 + nt * 8 + (lane & 3) * 2;
            float2 bb = make_float2(0.f, 0.f);
            if (BIAS) bb = *(const float2*)&bias[col];
            #pragma unroll
            for (int half = 0; half < 2; half++) {
                int row = rowBase + warpM * (MT * 16) + mt * 16 + (lane >> 2) + half * 8;
                if (row < M) {
                    float vx = acc[mt][nt][half * 2 + 0] + bb.x;
                    float vy = acc[mt][nt][half * 2 + 1] + bb.y;
                    if (RELU) { vx = fmaxf(vx, 0.f); vy = fmaxf(vy, 0.f); }
                    if (OUTBF) {
                        __nv_bfloat16 hx, hy; float lx, ly;
                        split_bf16(vx, hx, lx);
                        split_bf16(vy, hy, ly);
                        uint32_t ph = pack_bf16(__bfloat162float(hx), __bfloat162float(hy));
                        uint32_t pl = pack_bf16(lx, ly);
                        *(uint32_t*)&Chi[(size_t)row * Nout + col] = ph;
                        *(uint32_t*)&Clo[(size_t)row * Nout + col] = pl;
                    } else {
                        *(float2*)&C[(size_t)row * Nout + col] = make_float2(vx, vy);
                    }
                }
            }
        }
    }
}

// ---------------- aggregation (warp per node) ----------------
template <int D, bool BR, bool OUTBF>
__global__ __launch_bounds__(256) void k_agg(
        const float* __restrict__ t, const float* __restrict__ bias,
        float* __restrict__ outF, __nv_bfloat16* __restrict__ outHi,
        __nv_bfloat16* __restrict__ outLo, int n) {
    constexpr int V = D / 32;
    int node = (blockIdx.x * blockDim.x + threadIdx.x) >> 5;
    int lane = threadIdx.x & 31;
    if (node >= n) return;

    int deg = g_deg[node];
    float dn = rsqrtf((float)deg + 1.0f);
    int degR = (deg + 3) & ~3;

    float acc[V];
    {
        const float* trow = t + (size_t)node * D + lane * V;
        float w = dn * dn;
        if constexpr (V == 4) {
            float4 a = *(const float4*)trow;
            acc[0] = w * a.x; acc[1] = w * a.y; acc[2] = w * a.z; acc[3] = w * a.w;
        } else {
            float2 a = *(const float2*)trow;
            acc[0] = w * a.x; acc[1] = w * a.y;
        }
    }

    const int*   bi = &g_csrc[(size_t)node * CAP];
    const float* bw = &g_wgt [(size_t)node * CAP];
    for (int e = 0; e < degR; e += 4) {
        int4   s4 = *(const int4*)&bi[e];
        float4 w4 = *(const float4*)&bw[e];
        const float* r0 = t + (size_t)s4.x * D + lane * V;
        const float* r1 = t + (size_t)s4.y * D + lane * V;
        const float* r2 = t + (size_t)s4.z * D + lane * V;
        const float* r3 = t + (size_t)s4.w * D + lane * V;
        if constexpr (V == 4) {
            float4 v0 = *(const float4*)r0;
            float4 v1 = *(const float4*)r1;
            float4 v2 = *(const float4*)r2;
            float4 v3 = *(const float4*)r3;
            acc[0] = fmaf(w4.x, v0.x, acc[0]); acc[1] = fmaf(w4.x, v0.y, acc[1]);
            acc[2] = fmaf(w4.x, v0.z, acc[2]); acc[3] = fmaf(w4.x, v0.w, acc[3]);
            acc[0] = fmaf(w4.y, v1.x, acc[0]); acc[1] = fmaf(w4.y, v1.y, acc[1]);
            acc[2] = fmaf(w4.y, v1.z, acc[2]); acc[3] = fmaf(w4.y, v1.w, acc[3]);
            acc[0] = fmaf(w4.z, v2.x, acc[0]); acc[1] = fmaf(w4.z, v2.y, acc[1]);
            acc[2] = fmaf(w4.z, v2.z, acc[2]); acc[3] = fmaf(w4.z, v2.w, acc[3]);
            acc[0] = fmaf(w4.w, v3.x, acc[0]); acc[1] = fmaf(w4.w, v3.y, acc[1]);
            acc[2] = fmaf(w4.w, v3.z, acc[2]); acc[3] = fmaf(w4.w, v3.w, acc[3]);
        } else {
            float2 v0 = *(const float2*)r0;
            float2 v1 = *(const float2*)r1;
            float2 v2 = *(const float2*)r2;
            float2 v3 = *(const float2*)r3;
            acc[0] = fmaf(w4.x, v0.x, acc[0]); acc[1] = fmaf(w4.x, v0.y, acc[1]);
            acc[0] = fmaf(w4.y, v1.x, acc[0]); acc[1] = fmaf(w4.y, v1.y, acc[1]);
            acc[0] = fmaf(w4.z, v2.x, acc[0]); acc[1] = fmaf(w4.z, v2.y, acc[1]);
            acc[0] = fmaf(w4.w, v3.x, acc[0]); acc[1] = fmaf(w4.w, v3.y, acc[1]);
        }
    }

    float v[V];
    #pragma unroll
    for (int j = 0; j < V; j++) {
        float b = BR ? bias[lane * V + j] : 0.0f;
        float r = acc[j] + b;
        v[j] = BR ? fmaxf(r, 0.0f) : r;
    }
    if constexpr (OUTBF) {
        __nv_bfloat16 h[V]; float l[V];
        #pragma unroll
        for (int j = 0; j < V; j++) split_bf16(v[j], h[j], l[j]);
        if constexpr (V == 4) {
            uint2 ph, pl;
            ph.x = pack_bf16(__bfloat162float(h[0]), __bfloat162float(h[1]));
            ph.y = pack_bf16(__bfloat162float(h[2]), __bfloat162float(h[3]));
            pl.x = pack_bf16(l[0], l[1]); pl.y = pack_bf16(l[2], l[3]);
            *(uint2*)&outHi[(size_t)node * D + lane * 4] = ph;
            *(uint2*)&outLo[(size_t)node * D + lane * 4] = pl;
        } else {
            *(uint32_t*)&outHi[(size_t)node * D + lane * 2] =
                pack_bf16(__bfloat162float(h[0]), __bfloat162float(h[1]));
            *(uint32_t*)&outLo[(size_t)node * D + lane * 2] = pack_bf16(l[0], l[1]);
        }
    } else {
        if constexpr (V == 4)
            *(float4*)&outF[(size_t)node * D + lane * 4] =
                make_float4(v[0], v[1], v[2], v[3]);
        else
            *(float2*)&outF[(size_t)node * D + lane * 2] = make_float2(v[0], v[1]);
    }
}

// ---------------- launch ----------------
extern "C" void kernel_launch(void* const* d_in, const int* in_sizes, int n_in,
                              void* d_out, int out_size) {
    const float* x  = (const float*)d_in[0];
    const int*   ei = (const int*)d_in[1];
    const float* W1 = (const float*)d_in[3];
    const float* b1 = (const float*)d_in[4];
    const float* W2 = (const float*)d_in[5];
    const float* b2 = (const float*)d_in[6];
    const float* W3 = (const float*)d_in[7];
    const float* b3 = (const float*)d_in[8];
    const float* W4 = (const float*)d_in[9];
    const float* b4 = (const float*)d_in[10];
    const float* Wl = (const float*)d_in[11];
    const float* bl = (const float*)d_in[12];
    float* out = (float*)d_out;

    const int N = in_sizes[0] / 128;   // 40000
    const int E = in_sizes[1] / 2;     // 640000

    float *bufA, *bufB;
    __nv_bfloat16 *hi0, *lo0, *hi1, *lo1;
    uint32_t *bfH, *bfL;
    int* degP;
    cudaGetSymbolAddress((void**)&bufA, g_bufA);
    cudaGetSymbolAddress((void**)&bufB, g_bufB);
    cudaGetSymbolAddress((void**)&hi0, g_hi0);
    cudaGetSymbolAddress((void**)&lo0, g_lo0);
    cudaGetSymbolAddress((void**)&hi1, g_hi1);
    cudaGetSymbolAddress((void**)&lo1, g_lo1);
    cudaGetSymbolAddress((void**)&bfH, g_BfH);
    cudaGetSymbolAddress((void**)&bfL, g_BfL);
    cudaGetSymbolAddress((void**)&degP, g_deg);

    constexpr int SM_K128 = 2 * 128 * 128 * 2;   // 65536
    constexpr int SM_K64  = 2 * 128 * 64 * 2;    // 32768
    cudaFuncSetAttribute(k_gemm_mma<128, 64, false, false, false, true>,
                         cudaFuncAttributeMaxDynamicSharedMemorySize, SM_K128);
    cudaFuncSetAttribute(k_gemm_mma<128, 64, false, false, false, false>,
                         cudaFuncAttributeMaxDynamicSharedMemorySize, SM_K128);
    cudaFuncSetAttribute(k_gemm_mma<64, 64, true, true, true, false>,
                         cudaFuncAttributeMaxDynamicSharedMemorySize, SM_K64);
    cudaFuncSetAttribute(k_gemm_mma<64, 32, true, false, false, false>,
                         cudaFuncAttributeMaxDynamicSharedMemorySize, SM_K64);

    // side streams + events for fork-join (created once; capture-safe pattern)
    static cudaStream_t s1 = nullptr, s2 = nullptr;
    static cudaEvent_t e0 = nullptr, eA = nullptr, eB = nullptr;
    if (s1 == nullptr) {
        cudaStreamCreateWithFlags(&s1, cudaStreamNonBlocking);
        cudaStreamCreateWithFlags(&s2, cudaStreamNonBlocking);
        cudaEventCreateWithFlags(&e0, cudaEventDisableTiming);
        cudaEventCreateWithFlags(&eA, cudaEventDisableTiming);
        cudaEventCreateWithFlags(&eB, cudaEventDisableTiming);
    }

    const int aggBlocks = (N + 7) / 8;
    const int gy = (N + 127) / 128;

    // ---- fork: graph build (s1) || weight prep + L1 GEMM (s2) ----
    cudaEventRecord(e0, 0);
    cudaStreamWaitEvent(s1, e0, 0);
    cudaStreamWaitEvent(s2, e0, 0);

    cudaMemsetAsync(degP, 0, (size_t)N * sizeof(int), s1);
    k_fill<<<(E + 255) / 256, 256, 0, s1>>>(ei, E);
    k_wgt<<<((size_t)N * CAP + 255) / 256, 256, 0, s1>>>(N);

    k_prepAll<<<(10752 + 255) / 256, 256, 0, s2>>>(W1, W2, W3, W4, Wl);
    // L1: t1 = x @ W1 -> bufA(f32), fp32 input with inline split
    k_gemm_mma<128, 64, false, false, false, true><<<dim3(1, gy), 256, SM_K128, s2>>>(
        nullptr, nullptr, x, bfH + 0, bfL + 0, nullptr, bufA, nullptr, nullptr, N, 64);

    cudaEventRecord(eA, s1);
    cudaEventRecord(eB, s2);
    cudaStreamWaitEvent(0, eA, 0);
    cudaStreamWaitEvent(0, eB, 0);

    // ---- join: remaining serial chain on default stream ----
    // a1 = relu(agg(t1)+b1) -> bufB(f32)
    k_agg<64, true, false><<<aggBlocks, 256>>>(bufA, b1, bufB, nullptr, nullptr, N);

    // L2 (agg-first): u = agg(a1) -> hi0/lo0 ; a2 = relu(u@W2+b2) -> hi1/lo1
    k_agg<64, false, true><<<aggBlocks, 256>>>(bufB, nullptr, nullptr, hi0, lo0, N);
    k_gemm_mma<64, 64, true, true, true, false><<<dim3(2, gy), 256, SM_K64>>>(
        hi0, lo0, nullptr, bfH + 4096, bfL + 4096, b2, nullptr, hi1, lo1, N, 128);

    // L3: t3 = a2 @ W3 -> bufA(f32); a3 = relu(agg+b3) -> hi0/lo0
    k_gemm_mma<128, 64, false, false, false, false><<<dim3(2, gy), 256, SM_K128>>>(
        hi1, lo1, nullptr, bfH + 8192, bfL + 8192, nullptr, bufA, nullptr, nullptr, N, 128);
    k_agg<128, true, true><<<aggBlocks, 256>>>(bufA, b3, nullptr, hi0, lo0, N);

    // L4: t4 = a3 @ W4 -> bufA(f32); a4 = relu(agg+b4) -> hi1/lo1
    k_gemm_mma<128, 64, false, false, false, false><<<dim3(1, gy), 256, SM_K128>>>(
        hi0, lo0, nullptr, bfH + 16384, bfL + 16384, nullptr, bufA, nullptr, nullptr, N, 64);
    k_agg<64, true, true><<<aggBlocks, 256>>>(bufA, b4, nullptr, hi1, lo1, N);

    // L5: out = a4 @ Wl + bl
    k_gemm_mma<64, 32, true, false, false, false><<<dim3(1, gy), 256, SM_K64>>>(
        hi1, lo1, nullptr, bfH + 20480, bfL + 20480, bl, out, nullptr, nullptr, N, 32);
}